// round 9
// baseline (speedup 1.0000x reference)
#include <cuda_runtime.h>
#include <math.h>

typedef unsigned long long ull;

#define FEAT_DIM 360
#define MAXB     32
#define NT       320
#define TILE     32
#define ST       40              // smem row stride in floats
#define CHF      (38 * ST)       // per-channel buffer floats (38 rows)

__device__ float g_feat[MAXB * FEAT_DIM];

// ---------------- packed f32x2 helpers ----------------
__device__ __forceinline__ ull pack2(float lo, float hi) {
    ull r; asm("mov.b64 %0, {%1, %2};" : "=l"(r) : "f"(lo), "f"(hi)); return r;
}
__device__ __forceinline__ void unpack2(ull v, float& lo, float& hi) {
    asm("mov.b64 {%0, %1}, %2;" : "=f"(lo), "=f"(hi) : "l"(v));
}
__device__ __forceinline__ ull fma2(ull a, ull b, ull c) {
    ull r; asm("fma.rn.f32x2 %0, %1, %2, %3;" : "=l"(r) : "l"(a), "l"(b), "l"(c)); return r;
}
__device__ __forceinline__ ull mul2(ull a, ull b) {
    ull r; asm("mul.rn.f32x2 %0, %1, %2;" : "=l"(r) : "l"(a), "l"(b)); return r;
}
__device__ __forceinline__ ull add2(ull a, ull b) {
    ull r; asm("add.rn.f32x2 %0, %1, %2;" : "=l"(r) : "l"(a), "l"(b)); return r;
}

#define C06P 0x3F19999A3F19999AULL
#define C04P 0x3ECCCCCD3ECCCCCDULL
#define ONE2 0x3F8000003F800000ULL

// lrelu(v) = 0.6*v + 0.4*|v|  (exact), branch-free packed
__device__ __forceinline__ ull lrelu2(ull v) {
    ull a = v & 0x7FFFFFFF7FFFFFFFULL;
    return fma2(a, (ull)C04P, mul2(v, (ull)C06P));
}

// ---------------- merged preamble: mean(thumb) + GEMV ----------------
#define FT 384
__global__ void feat_kernel(const float* __restrict__ thumb,
                            const float* __restrict__ Wm,
                            const float* __restrict__ bm, int HW) {
    int b = blockIdx.x;
    int tid = threadIdx.x;
    __shared__ float red[FT / 32][3];
    __shared__ float m[3];
    const float4* p = (const float4*)(thumb + (size_t)b * 3 * HW);
    int n4c = HW / 4;
    float s[3];
    #pragma unroll
    for (int c = 0; c < 3; c++) {
        float acc = 0.0f;
        for (int i = tid; i < n4c; i += FT) {
            float4 v = p[c * n4c + i];
            acc += (v.x + v.y) + (v.z + v.w);
        }
        s[c] = acc;
    }
    #pragma unroll
    for (int c = 0; c < 3; c++) {
        float v = s[c];
        #pragma unroll
        for (int o = 16; o > 0; o >>= 1) v += __shfl_down_sync(0xffffffffu, v, o);
        if ((tid & 31) == 0) red[tid >> 5][c] = v;
    }
    __syncthreads();
    if (tid == 0) {
        float inv = 1.0f / (float)HW;
        #pragma unroll
        for (int c = 0; c < 3; c++) {
            float t = 0.0f;
            #pragma unroll
            for (int w = 0; w < FT / 32; w++) t += red[w][c];
            m[c] = t * inv;
        }
    }
    __syncthreads();
    if (tid < FEAT_DIM) {
        g_feat[b * FEAT_DIM + tid] =
            m[0] * Wm[tid] + m[1] * Wm[FEAT_DIM + tid] + m[2] * Wm[2 * FEAT_DIM + tid]
            + bm[tid];
    }
}

// ---------------- one 3x3 conv quad (4 horizontally adjacent pixels) ----------------
// Source reads at columns c-1..c+4 (c ODD -> three aligned LDS.64 per (ic,ky)).
// Produces two packed pairs per oc. STORE: write 4 floats per oc into dst frame.
// wPack layout: [oc*27 + ic*9 + ky*3 + kx], bias at 81..83.
template <bool STORE>
__device__ __forceinline__ void conv_quad(const float* __restrict__ src,
                                          float* __restrict__ dst,
                                          const ull* __restrict__ wPack,
                                          int row, int c,
                                          ull outA[3], ull outB[3]) {
    ull accA[3], accB[3];
    #pragma unroll
    for (int oc = 0; oc < 3; oc++) { accA[oc] = wPack[81 + oc]; accB[oc] = accA[oc]; }
    #pragma unroll
    for (int ic = 0; ic < 3; ic++) {
        #pragma unroll
        for (int ky = 0; ky < 3; ky++) {
            ull w00 = wPack[ 0 + ic * 9 + ky * 3 + 0];
            ull w01 = wPack[ 0 + ic * 9 + ky * 3 + 1];
            ull w02 = wPack[ 0 + ic * 9 + ky * 3 + 2];
            ull w10 = wPack[27 + ic * 9 + ky * 3 + 0];
            ull w11 = wPack[27 + ic * 9 + ky * 3 + 1];
            ull w12 = wPack[27 + ic * 9 + ky * 3 + 2];
            ull w20 = wPack[54 + ic * 9 + ky * 3 + 0];
            ull w21 = wPack[54 + ic * 9 + ky * 3 + 1];
            ull w22 = wPack[54 + ic * 9 + ky * 3 + 2];
            const float* s = src + ic * CHF + (row - 1 + ky) * ST + (c - 1);
            float2 e0 = *(const float2*)s;
            float2 e1 = *(const float2*)(s + 2);
            float2 e2 = *(const float2*)(s + 4);
            ull E0 = pack2(e0.x, e0.y);
            ull E1 = pack2(e1.x, e1.y);
            ull E2 = pack2(e2.x, e2.y);
            ull m1 = pack2(e0.y, e1.x);     // (s[c], s[c+1])
            ull m2 = pack2(e1.y, e2.x);     // (s[c+2], s[c+3])
            // pair A = pixels (c, c+1): taps E0, m1, E1
            accA[0] = fma2(w00, E0, accA[0]);
            accA[0] = fma2(w01, m1, accA[0]);
            accA[0] = fma2(w02, E1, accA[0]);
            accA[1] = fma2(w10, E0, accA[1]);
            accA[1] = fma2(w11, m1, accA[1]);
            accA[1] = fma2(w12, E1, accA[1]);
            accA[2] = fma2(w20, E0, accA[2]);
            accA[2] = fma2(w21, m1, accA[2]);
            accA[2] = fma2(w22, E1, accA[2]);
            // pair B = pixels (c+2, c+3): taps E1, m2, E2
            accB[0] = fma2(w00, E1, accB[0]);
            accB[0] = fma2(w01, m2, accB[0]);
            accB[0] = fma2(w02, E2, accB[0]);
            accB[1] = fma2(w10, E1, accB[1]);
            accB[1] = fma2(w11, m2, accB[1]);
            accB[1] = fma2(w12, E2, accB[1]);
            accB[2] = fma2(w20, E1, accB[2]);
            accB[2] = fma2(w21, m2, accB[2]);
            accB[2] = fma2(w22, E2, accB[2]);
        }
    }
    #pragma unroll
    for (int oc = 0; oc < 3; oc++) {
        ull rA = lrelu2(accA[oc]);
        ull rB = lrelu2(accB[oc]);
        if (STORE) {
            float* d = dst + oc * CHF + row * ST + c;
            float lo, hi;
            unpack2(rA, lo, hi); d[0] = lo; d[1] = hi;
            unpack2(rB, lo, hi); d[2] = lo; d[3] = hi;
        } else {
            outA[oc] = rA; outB[oc] = rB;
        }
    }
}

// dynamic smem: sPack (360 ull) | bufIn | bufL1 | bufL2 (each 3*CHF floats)
#define SMEM_BYTES (360 * 8 + 3 * (3 * CHF) * 4)

// ---------------- fused conv stack + attention ----------------
__global__ __launch_bounds__(NT, 3) void conv_att_kernel(
    const float* __restrict__ xMain, const float* __restrict__ xThumb,
    float* __restrict__ outAll, int Hm, int B, int tRowM) {
    extern __shared__ __align__(16) ull pool[];
    ull*   sPack = pool;
    float* bufIn = (float*)(pool + 360);
    float* bufL1 = bufIn + 3 * CHF;
    float* bufL2 = bufL1 + 3 * CHF;

    int mainTotal = B * tRowM * tRowM;
    int bid = blockIdx.x;
    const float* src; float* dst;
    int H, tRow, b, tile;
    if (bid < mainTotal) {
        int per = tRowM * tRowM;
        b = bid / per; tile = bid - b * per;
        H = Hm; tRow = tRowM;
        src = xMain + (size_t)b * 3 * H * H;
        dst = outAll + (size_t)b * 3 * H * H;
    } else {
        int r = bid - mainTotal;
        b = r >> 2; tile = r & 3;
        H = 64; tRow = 2;
        src = xThumb + (size_t)b * 3 * 64 * 64;
        dst = outAll + (size_t)B * 3 * Hm * Hm + (size_t)b * 3 * 64 * 64;
    }
    int ty = tile / tRow, tx = tile - ty * tRow;
    int y0 = ty * TILE, x0 = tx * TILE;
    int tid = threadIdx.x;

    // load input tile with halo 3 (zero-padded) into stride-40 frame;
    // independent of g_feat -> overlaps feat kernel under PDL.
    for (int i = tid; i < 3 * 38 * 38; i += NT) {
        int c = i / (38 * 38);
        int r = i - c * (38 * 38);
        int y = r / 38, xx = r - y * 38;
        int gy = y0 - 3 + y, gx = x0 - 3 + xx;
        float v = 0.0f;
        if (gy >= 0 && gy < H && gx >= 0 && gx < H)
            v = __ldg(&src[((size_t)c * H + gy) * H + gx]);
        bufIn[c * CHF + y * ST + xx] = v;
    }

    cudaGridDependencySynchronize();
    for (int j = tid; j < FEAT_DIM; j += NT) {
        float f = g_feat[b * FEAT_DIM + j];
        sPack[j] = pack2(f, f);
    }
    __syncthreads();

    // L1: bufIn -> bufL1. 324 quads: rows 1..36, 9 quads/row at c=1+4*qx.
    {
        int q = tid;                       // all 320 threads: q < 324
        int row = q / 9 + 1, c = 1 + 4 * (q - (q / 9) * 9);
        conv_quad<true>(bufIn, bufL1, sPack, row, c, (ull*)nullptr, (ull*)nullptr);
        if (tid < 4) {
            int q2 = 320 + tid;
            int row2 = q2 / 9 + 1, c2 = 1 + 4 * (q2 - (q2 / 9) * 9);
            conv_quad<true>(bufIn, bufL1, sPack, row2, c2, (ull*)nullptr, (ull*)nullptr);
        }
    }
    __syncthreads();

    // L2: bufL1 -> bufL2, same 324-quad geometry (border quads compute garbage
    // from never-written bufL1 frame cells; those outputs are never consumed).
    {
        int q = tid;
        int row = q / 9 + 1, c = 1 + 4 * (q - (q / 9) * 9);
        conv_quad<true>(bufL1, bufL2, sPack + 84, row, c, (ull*)nullptr, (ull*)nullptr);
        if (tid < 4) {
            int q2 = 320 + tid;
            int row2 = q2 / 9 + 1, c2 = 1 + 4 * (q2 - (q2 / 9) * 9);
            conv_quad<true>(bufL1, bufL2, sPack + 84, row2, c2, (ull*)nullptr, (ull*)nullptr);
        }
    }
    __syncthreads();

    // L3 + epilogue: 256 quads (rows 3..34, 8 quads/row at c=3+4*qx), 1/thread.
    if (tid < 256) {
        int row = (tid >> 3) + 3, c = 3 + 4 * (tid & 7);
        ull curA[3], curB[3];
        conv_quad<false>(bufL2, (float*)nullptr, sPack + 168, row, c, curA, curB);

        // 5x conv1x1 (packed, in registers)
        #pragma unroll
        for (int l = 0; l < 5; l++) {
            const ull* wl = sPack + 252 + l * 12;
            ull W0 = wl[0], W1 = wl[1], W2 = wl[2];
            ull W3 = wl[3], W4 = wl[4], W5 = wl[5];
            ull W6 = wl[6], W7 = wl[7], W8 = wl[8];
            ull B0 = wl[9], B1 = wl[10], B2 = wl[11];
            {
                ull c0 = curA[0], c1 = curA[1], c2 = curA[2];
                ull n0 = fma2(W0, c0, fma2(W1, c1, fma2(W2, c2, B0)));
                ull n1 = fma2(W3, c0, fma2(W4, c1, fma2(W5, c2, B1)));
                ull n2 = fma2(W6, c0, fma2(W7, c1, fma2(W8, c2, B2)));
                curA[0] = lrelu2(n0); curA[1] = lrelu2(n1); curA[2] = lrelu2(n2);
            }
            {
                ull c0 = curB[0], c1 = curB[1], c2 = curB[2];
                ull n0 = fma2(W0, c0, fma2(W1, c1, fma2(W2, c2, B0)));
                ull n1 = fma2(W3, c0, fma2(W4, c1, fma2(W5, c2, B1)));
                ull n2 = fma2(W6, c0, fma2(W7, c1, fma2(W8, c2, B2)));
                curB[0] = lrelu2(n0); curB[1] = lrelu2(n1); curB[2] = lrelu2(n2);
            }
        }

        // residual (from intact bufIn) + polynomial attention + store
        int gy = y0 + row - 3, gx = x0 + c - 3;      // gx even
        float invH = 1.0f / (float)H;
        float hv = (float)gy * invH;
        ull hP  = pack2(hv, hv);
        ull wPA = pack2((float)gx * invH, (float)(gx + 1) * invH);
        ull wPB = pack2((float)(gx + 2) * invH, (float)(gx + 3) * invH);
        #pragma unroll
        for (int oc = 0; oc < 3; oc++) {
            const float* s = bufIn + oc * CHF + row * ST + (c - 1);
            float2 e0 = *(const float2*)s;
            float2 e1 = *(const float2*)(s + 2);
            float2 e2 = *(const float2*)(s + 4);
            ull vA = add2(pack2(e0.y, e1.x), curA[oc]);
            ull vB = add2(pack2(e1.y, e2.x), curB[oc]);
            ull attA = (ull)ONE2, attB = (ull)ONE2;
            #pragma unroll
            for (int i = 0; i < 4; i++) {
                const ull* f = sPack + 312 + oc * 16 + i * 4;
                attA = mul2(attA, fma2(f[0], hP, fma2(f[1], wPA, fma2(f[2], vA, f[3]))));
                attB = mul2(attB, fma2(f[0], hP, fma2(f[1], wPB, fma2(f[2], vB, f[3]))));
            }
            ull rA = mul2(vA, add2((ull)ONE2, attA));
            ull rB = mul2(vB, add2((ull)ONE2, attB));
            float* o = &dst[((size_t)oc * H + gy) * H + gx];
            *(ull*)o       = rA;
            *(ull*)(o + 2) = rB;
        }
    }
}

// ---------------- launch ----------------
extern "C" void kernel_launch(void* const* d_in, const int* in_sizes, int n_in,
                              void* d_out, int out_size) {
    const float* x     = (const float*)d_in[0];
    const float* thumb = (const float*)d_in[1];
    const float* Wm    = (const float*)d_in[2];
    const float* bm    = (const float*)d_in[3];
    float* out = (float*)d_out;

    int Ht = 64;
    int B  = in_sizes[1] / (3 * Ht * Ht);
    if (B < 1) B = 1;
    if (B > MAXB) B = MAXB;
    int hw = in_sizes[0] / (3 * B);
    int Hm = (int)(sqrt((double)hw) + 0.5);

    cudaFuncSetAttribute(conv_att_kernel,
                         cudaFuncAttributeMaxDynamicSharedMemorySize, SMEM_BYTES);

    feat_kernel<<<B, FT>>>(thumb, Wm, bm, Ht * Ht);

    int tRowM = Hm / TILE;
    int total = B * tRowM * tRowM + B * 4;

    cudaLaunchConfig_t cfg = {};
    cfg.gridDim = dim3(total);
    cfg.blockDim = dim3(NT);
    cfg.dynamicSmemBytes = SMEM_BYTES;
    cfg.stream = 0;
    cudaLaunchAttribute attrs[1];
    attrs[0].id = cudaLaunchAttributeProgrammaticStreamSerialization;
    attrs[0].val.programmaticStreamSerializationAllowed = 1;
    cfg.attrs = attrs;
    cfg.numAttrs = 1;
    cudaLaunchKernelEx(&cfg, conv_att_kernel, x, thumb, out, Hm, B, tRowM);
}

// round 10
// speedup vs baseline: 1.6064x; 1.6064x over previous
#include <cuda_runtime.h>
#include <math.h>

typedef unsigned long long ull;

#define FEAT_DIM 360
#define MAXB     32
#define NT       256
#define TILE     32

__device__ float g_feat[MAXB * FEAT_DIM];

// ---------------- packed f32x2 helpers ----------------
__device__ __forceinline__ ull pack2(float lo, float hi) {
    ull r; asm("mov.b64 %0, {%1, %2};" : "=l"(r) : "f"(lo), "f"(hi)); return r;
}
__device__ __forceinline__ ull fma2(ull a, ull b, ull c) {
    ull r; asm("fma.rn.f32x2 %0, %1, %2, %3;" : "=l"(r) : "l"(a), "l"(b), "l"(c)); return r;
}
__device__ __forceinline__ ull mul2(ull a, ull b) {
    ull r; asm("mul.rn.f32x2 %0, %1, %2;" : "=l"(r) : "l"(a), "l"(b)); return r;
}
__device__ __forceinline__ ull add2(ull a, ull b) {
    ull r; asm("add.rn.f32x2 %0, %1, %2;" : "=l"(r) : "l"(a), "l"(b)); return r;
}
// (hi(a), lo(b)) -- exactly 2 register moves, no shifts
__device__ __forceinline__ ull mid2(ull a, ull b) {
    ull r;
    asm("{\n\t"
        ".reg .b32 al, ah, bl, bh;\n\t"
        "mov.b64 {al, ah}, %1;\n\t"
        "mov.b64 {bl, bh}, %2;\n\t"
        "mov.b64 %0, {ah, bl};\n\t"
        "}" : "=l"(r) : "l"(a), "l"(b));
    return r;
}

#define C06P 0x3F19999A3F19999AULL   // (0.6f, 0.6f)
#define C04P 0x3ECCCCCD3ECCCCCDULL   // (0.4f, 0.4f)
#define ONE2 0x3F8000003F800000ULL   // (1.0f, 1.0f)

// lrelu(v) = 0.6*v + 0.4*|v|  (exact), branch-free packed
__device__ __forceinline__ ull lrelu2(ull v) {
    ull a = v & 0x7FFFFFFF7FFFFFFFULL;
    return fma2(a, (ull)C04P, mul2(v, (ull)C06P));
}

// ---------------- merged preamble: mean(thumb) + GEMV, one launch ----------------
#define FT 384
__global__ void feat_kernel(const float* __restrict__ thumb,
                            const float* __restrict__ Wm,
                            const float* __restrict__ bm, int HW) {
    int b = blockIdx.x;
    int tid = threadIdx.x;
    __shared__ float red[FT / 32][3];
    __shared__ float m[3];
    const float4* p = (const float4*)(thumb + (size_t)b * 3 * HW);
    int n4c = HW / 4;
    float s[3];
    #pragma unroll
    for (int c = 0; c < 3; c++) {
        float acc = 0.0f;
        for (int i = tid; i < n4c; i += FT) {
            float4 v = p[c * n4c + i];
            acc += (v.x + v.y) + (v.z + v.w);
        }
        s[c] = acc;
    }
    #pragma unroll
    for (int c = 0; c < 3; c++) {
        float v = s[c];
        #pragma unroll
        for (int o = 16; o > 0; o >>= 1) v += __shfl_down_sync(0xffffffffu, v, o);
        if ((tid & 31) == 0) red[tid >> 5][c] = v;
    }
    __syncthreads();
    if (tid == 0) {
        float inv = 1.0f / (float)HW;
        #pragma unroll
        for (int c = 0; c < 3; c++) {
            float t = 0.0f;
            #pragma unroll
            for (int w = 0; w < FT / 32; w++) t += red[w][c];
            m[c] = t * inv;
        }
    }
    __syncthreads();
    if (tid < FEAT_DIM) {
        g_feat[b * FEAT_DIM + tid] =
            m[0] * Wm[tid] + m[1] * Wm[FEAT_DIM + tid] + m[2] * Wm[2 * FEAT_DIM + tid]
            + bm[tid];
    }
}

// ---------------- one 3x3 conv layer on pixel pairs ----------------
// v0/v2 loaded directly as 64-bit (no packing); only v1 pays 2 MOVs via mid2.
// Requires even-pixel alignment of every pair -> all ull LDS are 8B-aligned.
template <int S, int D, int SLOTS, bool STORE>
__device__ __forceinline__ void conv3_pairs(const float* __restrict__ src,
                                            float* __restrict__ dst,
                                            const ull* __restrict__ wPack,
                                            int tid, ull outReg[][3]) {
    constexpr int PW = D / 2;
    constexpr int NP = D * PW;
    int off[SLOTS];
    #pragma unroll
    for (int k = 0; k < SLOTS; k++) {
        int p = tid + k * NT;
        int y = p / PW, x = (p - y * PW) * 2;
        off[k] = y * S + x;
    }
    ull acc[SLOTS][3];
    #pragma unroll
    for (int oc = 0; oc < 3; oc++) {
        ull bb = wPack[81 + oc];
        #pragma unroll
        for (int k = 0; k < SLOTS; k++) acc[k][oc] = bb;
    }
    #pragma unroll
    for (int ic = 0; ic < 3; ic++) {
        #pragma unroll
        for (int ky = 0; ky < 3; ky++) {
            ull w00 = wPack[ 0 + ic * 9 + ky * 3 + 0];
            ull w01 = wPack[ 0 + ic * 9 + ky * 3 + 1];
            ull w02 = wPack[ 0 + ic * 9 + ky * 3 + 2];
            ull w10 = wPack[27 + ic * 9 + ky * 3 + 0];
            ull w11 = wPack[27 + ic * 9 + ky * 3 + 1];
            ull w12 = wPack[27 + ic * 9 + ky * 3 + 2];
            ull w20 = wPack[54 + ic * 9 + ky * 3 + 0];
            ull w21 = wPack[54 + ic * 9 + ky * 3 + 1];
            ull w22 = wPack[54 + ic * 9 + ky * 3 + 2];
            #pragma unroll
            for (int k = 0; k < SLOTS; k++) {
                bool active = ((k + 1) * NT <= NP) || (tid + k * NT < NP);
                if (active) {
                    const float* s = src + ic * S * S + ky * S + off[k];
                    // NOTE: pairs start at even x AND (S even) rows keep parity,
                    // but x offset within row is even while (ky*S + off) may be
                    // odd in FLOAT units; alignment in bytes requires the float
                    // address to be 8B aligned: ic*S*S + ky*S + off is even for
                    // even S (36/38/34 all even) and even off. OK.
                    ull v0 = *(const ull*)s;
                    ull v2 = *(const ull*)(s + 2);
                    ull v1 = mid2(v0, v2);
                    acc[k][0] = fma2(w00, v0, acc[k][0]);
                    acc[k][0] = fma2(w01, v1, acc[k][0]);
                    acc[k][0] = fma2(w02, v2, acc[k][0]);
                    acc[k][1] = fma2(w10, v0, acc[k][1]);
                    acc[k][1] = fma2(w11, v1, acc[k][1]);
                    acc[k][1] = fma2(w12, v2, acc[k][1]);
                    acc[k][2] = fma2(w20, v0, acc[k][2]);
                    acc[k][2] = fma2(w21, v1, acc[k][2]);
                    acc[k][2] = fma2(w22, v2, acc[k][2]);
                }
            }
        }
    }
    #pragma unroll
    for (int k = 0; k < SLOTS; k++) {
        int p = tid + k * NT;
        bool active = ((k + 1) * NT <= NP) || (p < NP);
        if (active) {
            int y = p / PW, x = (p - y * PW) * 2;
            #pragma unroll
            for (int oc = 0; oc < 3; oc++) {
                ull r = lrelu2(acc[k][oc]);
                if (STORE) *(ull*)(dst + oc * D * D + y * D + x) = r;
                else       outReg[k][oc] = r;
            }
        }
    }
}

// ---------------- fused conv stack + attention (main + thumb merged) ----------------
__global__ __launch_bounds__(NT, 3) void conv_att_kernel(
    const float* __restrict__ xMain, const float* __restrict__ xThumb,
    float* __restrict__ outAll, int Hm, int B, int tRowM) {
    __shared__ __align__(16) float bufA[3 * 38 * 38];
    __shared__ __align__(16) float bufB[3 * 36 * 36];
    __shared__ ull sPack[FEAT_DIM];

    int mainTotal = B * tRowM * tRowM;
    int bid = blockIdx.x;
    const float* src; float* dst;
    int H, tRow, b, tile;
    if (bid < mainTotal) {
        int per = tRowM * tRowM;
        b = bid / per; tile = bid - b * per;
        H = Hm; tRow = tRowM;
        src = xMain + (size_t)b * 3 * H * H;
        dst = outAll + (size_t)b * 3 * H * H;
    } else {
        int r = bid - mainTotal;
        b = r >> 2; tile = r & 3;
        H = 64; tRow = 2;
        src = xThumb + (size_t)b * 3 * 64 * 64;
        dst = outAll + (size_t)B * 3 * Hm * Hm + (size_t)b * 3 * 64 * 64;
    }
    int ty = tile / tRow, tx = tile - ty * tRow;
    int y0 = ty * TILE, x0 = tx * TILE;
    int tid = threadIdx.x;

    // load input tile with halo 3 (zero-padded) -- overlaps feat kernel (PDL)
    for (int i = tid; i < 3 * 38 * 38; i += NT) {
        int c = i / (38 * 38);
        int r = i - c * (38 * 38);
        int y = r / 38, xx = r - y * 38;
        int gy = y0 - 3 + y, gx = x0 - 3 + xx;
        float v = 0.0f;
        if (gy >= 0 && gy < H && gx >= 0 && gx < H)
            v = __ldg(&src[((size_t)c * H + gy) * H + gx]);
        bufA[i] = v;
    }

    // wait for feat_kernel's g_feat writes, then splat features
    cudaGridDependencySynchronize();
    for (int j = tid; j < FEAT_DIM; j += NT) {
        float f = g_feat[b * FEAT_DIM + j];
        sPack[j] = pack2(f, f);
    }
    __syncthreads();

    // L1: bufA(38) -> bufB(36)
    conv3_pairs<38, 36, 3, true>(bufA, bufB, sPack, tid, (ull(*)[3])nullptr);

    // stash residual pairs: center starts at col 3 (odd) -> use mid2 of the
    // two aligned ull loads at cols 2 and 4.
    ull resP[2][3];
    #pragma unroll
    for (int k = 0; k < 2; k++) {
        int p = tid + k * NT;
        int y = p >> 4, x = (p & 15) * 2;
        #pragma unroll
        for (int oc = 0; oc < 3; oc++) {
            const float* q = &bufA[(oc * 38 + 3 + y) * 38 + 2 + x];
            ull e0 = *(const ull*)q;
            ull e1 = *(const ull*)(q + 2);
            resP[k][oc] = mid2(e0, e1);
        }
    }
    __syncthreads();

    // L2: bufB(36) -> bufA(34)
    conv3_pairs<36, 34, 3, true>(bufB, bufA, sPack + 84, tid, (ull(*)[3])nullptr);
    __syncthreads();

    // L3: bufA(34) -> registers (2 pair-slots/thread, exactly 32x32 tile)
    ull cur[2][3];
    conv3_pairs<34, 32, 2, false>(bufA, (float*)nullptr, sPack + 168, tid, cur);

    // 5x conv1x1 (packed, in registers)
    #pragma unroll
    for (int l = 0; l < 5; l++) {
        const ull* wl = sPack + 252 + l * 12;
        ull W0 = wl[0], W1 = wl[1], W2 = wl[2];
        ull W3 = wl[3], W4 = wl[4], W5 = wl[5];
        ull W6 = wl[6], W7 = wl[7], W8 = wl[8];
        ull B0 = wl[9], B1 = wl[10], B2 = wl[11];
        #pragma unroll
        for (int k = 0; k < 2; k++) {
            ull c0 = cur[k][0], c1 = cur[k][1], c2 = cur[k][2];
            ull n0 = fma2(W0, c0, fma2(W1, c1, fma2(W2, c2, B0)));
            ull n1 = fma2(W3, c0, fma2(W4, c1, fma2(W5, c2, B1)));
            ull n2 = fma2(W6, c0, fma2(W7, c1, fma2(W8, c2, B2)));
            cur[k][0] = lrelu2(n0);
            cur[k][1] = lrelu2(n1);
            cur[k][2] = lrelu2(n2);
        }
    }
    // residual add
    #pragma unroll
    for (int k = 0; k < 2; k++)
        #pragma unroll
        for (int oc = 0; oc < 3; oc++)
            cur[k][oc] = add2(resP[k][oc], cur[k][oc]);

    // polynomial attention + store (packed, 2 pixels per store)
    float invH = 1.0f / (float)H;
    #pragma unroll
    for (int k = 0; k < 2; k++) {
        int p = tid + k * NT;
        int y = p >> 4, x = (p & 15) * 2;
        int gy = y0 + y, gx = x0 + x;
        float hv = (float)gy * invH;
        ull hP = pack2(hv, hv);
        ull wP = pack2((float)gx * invH, (float)(gx + 1) * invH);
        #pragma unroll
        for (int oc = 0; oc < 3; oc++) {
            ull v = cur[k][oc];
            ull att = (ull)ONE2;
            #pragma unroll
            for (int i = 0; i < 4; i++) {
                const ull* f = sPack + 312 + oc * 16 + i * 4;
                ull t = fma2(f[0], hP, fma2(f[1], wP, fma2(f[2], v, f[3])));
                att = mul2(att, t);
            }
            ull r = mul2(v, add2((ull)ONE2, att));
            *(ull*)&dst[((size_t)oc * H + gy) * H + gx] = r;
        }
    }
}

// ---------------- launch ----------------
extern "C" void kernel_launch(void* const* d_in, const int* in_sizes, int n_in,
                              void* d_out, int out_size) {
    const float* x     = (const float*)d_in[0];
    const float* thumb = (const float*)d_in[1];
    const float* Wm    = (const float*)d_in[2];
    const float* bm    = (const float*)d_in[3];
    float* out = (float*)d_out;

    int Ht = 64;
    int B  = in_sizes[1] / (3 * Ht * Ht);
    if (B < 1) B = 1;
    if (B > MAXB) B = MAXB;
    int hw = in_sizes[0] / (3 * B);
    int Hm = (int)(sqrt((double)hw) + 0.5);

    feat_kernel<<<B, FT>>>(thumb, Wm, bm, Ht * Ht);

    int tRowM = Hm / TILE;
    int total = B * tRowM * tRowM + B * 4;

    cudaLaunchConfig_t cfg = {};
    cfg.gridDim = dim3(total);
    cfg.blockDim = dim3(NT);
    cfg.dynamicSmemBytes = 0;
    cfg.stream = 0;
    cudaLaunchAttribute attrs[1];
    attrs[0].id = cudaLaunchAttributeProgrammaticStreamSerialization;
    attrs[0].val.programmaticStreamSerializationAllowed = 1;
    cfg.attrs = attrs;
    cfg.numAttrs = 1;
    cudaLaunchKernelEx(&cfg, conv_att_kernel, x, thumb, out, Hm, B, tRowM);
}